// round 15
// baseline (speedup 1.0000x reference)
#include <cuda_runtime.h>
#include <cuda_fp16.h>
#include <cstdint>

#define NHEAD 6
#define DHEAD 64
#define CEMB  384
#define BB    256
#define TT    256
#define MROWS 65536

// ---------------- scratch (device globals: allocation-guard-safe) ----------
__device__ __align__(16) __half g_xhi[(size_t)MROWS * CEMB];    // x split
__device__ __align__(16) __half g_xlo[(size_t)MROWS * CEMB];
__device__ __align__(16) __half g_ahi[(size_t)MROWS * CEMB];    // attn out split
__device__ __align__(16) __half g_alo[(size_t)MROWS * CEMB];
__device__ __align__(16) __half g_wqh[(size_t)3 * CEMB * CEMB]; // Wqkv^T hi
__device__ __align__(16) __half g_wph[(size_t)CEMB * CEMB];     // Wproj^T hi
// q split, k/v hi only; layout [(b*NHEAD+h)*TT + t]*DHEAD + d
__device__ __align__(16) __half g_qh[(size_t)BB * NHEAD * TT * DHEAD];
__device__ __align__(16) __half g_ql[(size_t)BB * NHEAD * TT * DHEAD];
__device__ __align__(16) __half g_kh[(size_t)BB * NHEAD * TT * DHEAD];
__device__ __align__(16) __half g_vh[(size_t)BB * NHEAD * TT * DHEAD];

// ---------------- PTX helpers ----------------------------------------------
__device__ __forceinline__ uint32_t smem_u32(const void* p) {
    uint32_t a;
    asm("{ .reg .u64 t; cvta.to.shared.u64 t, %1; cvt.u32.u64 %0, t; }"
        : "=r"(a) : "l"(p));
    return a;
}

#define CP16(dst, src) \
    asm volatile("cp.async.cg.shared.global [%0], [%1], 16;" \
                 :: "r"(dst), "l"(src))

#define LDSM4(r0, r1, r2, r3, addr) \
    asm volatile("ldmatrix.sync.aligned.m8n8.x4.shared.b16 {%0,%1,%2,%3}, [%4];" \
                 : "=r"(r0), "=r"(r1), "=r"(r2), "=r"(r3) : "r"(addr))

#define LDSM4T(r0, r1, r2, r3, addr) \
    asm volatile("ldmatrix.sync.aligned.m8n8.x4.trans.shared.b16 {%0,%1,%2,%3}, [%4];" \
                 : "=r"(r0), "=r"(r1), "=r"(r2), "=r"(r3) : "r"(addr))

#define MMA16816(d, a, b0v, b1v) \
    asm volatile("mma.sync.aligned.m16n8k16.row.col.f32.f16.f16.f32 " \
                 "{%0,%1,%2,%3},{%4,%5,%6,%7},{%8,%9},{%0,%1,%2,%3};" \
                 : "+f"((d)[0]), "+f"((d)[1]), "+f"((d)[2]), "+f"((d)[3]) \
                 : "r"((a)[0]), "r"((a)[1]), "r"((a)[2]), "r"((a)[3]), \
                   "r"(b0v), "r"(b1v))

__device__ __forceinline__ uint32_t pk2f(float a, float b) {
    __half2 t = __floats2half2_rn(a, b);
    return *reinterpret_cast<uint32_t*>(&t);
}
__device__ __forceinline__ uint32_t pk2lo(float a, float b) {
    float ra = a - __half2float(__float2half_rn(a));
    float rb = b - __half2float(__float2half_rn(b));
    return pk2f(ra, rb);
}

// ---------------- conversion kernels ---------------------------------------
__global__ __launch_bounds__(256) void conv_split(const float* __restrict__ in) {
    const int i = blockIdx.x * 256 + threadIdx.x;
    float4 v = ((const float4*)in)[i];
    uint2 hp, lp;
    hp.x = pk2f(v.x, v.y); hp.y = pk2f(v.z, v.w);
    lp.x = pk2lo(v.x, v.y); lp.y = pk2lo(v.z, v.w);
    ((uint2*)g_xhi)[i] = hp;
    ((uint2*)g_xlo)[i] = lp;
}

template <int NN>
__global__ void conv_wT(const float* __restrict__ W) {
    const int n = blockIdx.x;
    const int k = threadIdx.x;
    float v = W[(size_t)k * NN + n];
    if (NN == 3 * CEMB) g_wqh[(size_t)n * CEMB + k] = __float2half_rn(v);
    else                g_wph[(size_t)n * CEMB + k] = __float2half_rn(v);
}

// ---------------- split-fp16 HMMA GEMM (2-term: [xh|xl] x [wh|wh]) ----------
// MODE 0: scatter D into g_qh/g_ql/g_kh/g_vh.  MODE 1: D + bias -> out.
#define GSMEM_BYTES (65536 + 1024)

template <int MODE>
__global__ __launch_bounds__(256) void gemm_mma(const float* __restrict__ bias,
                                                float* __restrict__ out) {
    extern __shared__ char dynraw[];
    char* sm = (char*)((((uintptr_t)dynraw) + 1023) & ~(uintptr_t)1023);
    const uint32_t smb = smem_u32(sm);

    const int tid = threadIdx.x;
    const int lane = tid & 31, wid = tid >> 5;
    const int wm = (wid & 3) * 32;
    const int wn = (wid >> 2) * 64;
    const int bn = blockIdx.x * 128, bm = blockIdx.y * 128;

    const __half* Ah = (MODE == 0) ? g_xhi : g_ahi;
    const __half* Al = (MODE == 0) ? g_xlo : g_alo;
    const __half* Bh = (MODE == 0) ? g_wqh : g_wph;

    const int a_row = (lane & 7) + ((lane >> 3) & 1) * 8;
    const int a_colh = (lane >> 4) * 16;
    const int b_row = (lane & 7) + ((lane >> 4) & 1) * 8;
    const int b_colh = ((lane >> 3) & 1) * 16;

    const int g_row0 = tid >> 3;
    const int g_c16 = tid & 7;
    const uint32_t g_dcol = (uint32_t)(g_c16 * 16);

    float acc[2][8][4];
#pragma unroll
    for (int mf = 0; mf < 2; mf++)
#pragma unroll
        for (int nf = 0; nf < 8; nf++)
#pragma unroll
            for (int i = 0; i < 4; i++) acc[mf][nf][i] = 0.f;

    {
#pragma unroll
        for (int p = 0; p < 4; p++) {
            const int r = g_row0 + p * 32;
            const uint32_t d = smb + r * 128 + (g_dcol ^ (uint32_t)((r & 7) << 4));
            CP16(d, Ah + (size_t)(bm + r) * CEMB + g_c16 * 8);
            CP16(d + 16384, Bh + (size_t)(bn + r) * CEMB + g_c16 * 8);
        }
        asm volatile("cp.async.commit_group;" ::: "memory");
    }

#pragma unroll 1
    for (int c = 0; c < 12; c++) {
        if (c + 1 < 12) {
            const int cn = c + 1;
            const int blk = cn / 6, cb = cn - blk * 6;
            const __half* As = blk ? Al : Ah;
            const uint32_t sbase = smb + (uint32_t)((cn & 1) * 32768);
#pragma unroll
            for (int p = 0; p < 4; p++) {
                const int r = g_row0 + p * 32;
                const uint32_t d = sbase + r * 128 + (g_dcol ^ (uint32_t)((r & 7) << 4));
                CP16(d, As + (size_t)(bm + r) * CEMB + cb * 64 + g_c16 * 8);
                CP16(d + 16384, Bh + (size_t)(bn + r) * CEMB + cb * 64 + g_c16 * 8);
            }
            asm volatile("cp.async.commit_group;" ::: "memory");
            asm volatile("cp.async.wait_group 1;" ::: "memory");
        } else {
            asm volatile("cp.async.wait_group 0;" ::: "memory");
        }
        __syncthreads();

        const uint32_t abase = smb + (uint32_t)((c & 1) * 32768);
        const uint32_t bbase = abase + 16384;

#pragma unroll
        for (int ks = 0; ks < 4; ks++) {
            uint32_t af[2][4];
#pragma unroll
            for (int mf = 0; mf < 2; mf++) {
                const int r = wm + mf * 16 + a_row;
                const uint32_t col = (uint32_t)(ks * 32 + a_colh);
                const uint32_t ad = abase + r * 128 + (col ^ (uint32_t)((r & 7) << 4));
                LDSM4(af[mf][0], af[mf][1], af[mf][2], af[mf][3], ad);
            }
            uint32_t bf[8][2];
#pragma unroll
            for (int g = 0; g < 4; g++) {
                const int r = wn + g * 16 + b_row;
                const uint32_t col = (uint32_t)(ks * 32 + b_colh);
                const uint32_t bd = bbase + r * 128 + (col ^ (uint32_t)((r & 7) << 4));
                LDSM4(bf[2 * g][0], bf[2 * g][1], bf[2 * g + 1][0], bf[2 * g + 1][1], bd);
            }
#pragma unroll
            for (int mf = 0; mf < 2; mf++)
#pragma unroll
                for (int nf = 0; nf < 8; nf++)
                    MMA16816(acc[mf][nf], af[mf], bf[nf][0], bf[nf][1]);
        }
        __syncthreads();
    }

    if (MODE == 0) {
        const int sec = bn / CEMB;
        const int cc0 = bn - sec * CEMB;
        __half* dh = (sec == 0) ? g_qh : (sec == 1) ? g_kh : g_vh;
#pragma unroll
        for (int mf = 0; mf < 2; mf++) {
            const int m0 = bm + wm + mf * 16 + (lane >> 2);
#pragma unroll
            for (int nf = 0; nf < 8; nf++) {
                const int cc = cc0 + wn + nf * 8 + (lane & 3) * 2;
                const int h = cc >> 6, d = cc & 63;
#pragma unroll
                for (int hf = 0; hf < 2; hf++) {
                    const int m = m0 + hf * 8;
                    const int b = m >> 8, t = m & 255;
                    const float v0 = acc[mf][nf][hf * 2], v1 = acc[mf][nf][hf * 2 + 1];
                    const size_t idx = (((size_t)b * NHEAD + h) * TT + t) * DHEAD + d;
                    *(uint32_t*)&dh[idx] = pk2f(v0, v1);
                    if (sec == 0)
                        *(uint32_t*)&g_ql[idx] = pk2lo(v0, v1);
                }
            }
        }
    } else {
#pragma unroll
        for (int mf = 0; mf < 2; mf++) {
            const int m0 = bm + wm + mf * 16 + (lane >> 2);
#pragma unroll
            for (int nf = 0; nf < 8; nf++) {
                const int col = bn + wn + nf * 8 + (lane & 3) * 2;
                const float b0 = bias[col], b1 = bias[col + 1];
#pragma unroll
                for (int hf = 0; hf < 2; hf++) {
                    const int m = m0 + hf * 8;
                    float2 v = make_float2(acc[mf][nf][hf * 2] + b0,
                                           acc[mf][nf][hf * 2 + 1] + b1);
                    *(float2*)&out[(size_t)m * CEMB + col] = v;
                }
            }
        }
    }
}

// ---------------- split-fp16 mma flash attention -----------------------------
// grid (qtile=2, bh=1536), 8 warps; warp = 16 query rows x all keys.
// smem: QH 0, QL 16K (persistent), KH 32K, VH 40K (chunk-staged)
#define ASM_QH 0
#define ASM_QL 16384
#define ASM_KH 32768
#define ASM_VH 40960
#define ASMEM_BYTES 49152

__global__ __launch_bounds__(256) void attn_mma() {
    extern __shared__ __align__(16) char asm_raw[];
    const uint32_t smb = smem_u32(asm_raw);

    const int tid = threadIdx.x;
    const int lane = tid & 31, w = tid >> 5;
    const int qt = blockIdx.x;          // 0..1
    const int bh = blockIdx.y;          // 0..1535

    const size_t hbase = (size_t)bh * TT * DHEAD;
    const __half* qgh = g_qh + hbase + (size_t)qt * 128 * DHEAD;
    const __half* qgl = g_ql + hbase + (size_t)qt * 128 * DHEAD;

    // stage Q (hi+lo) into persistent smem
    {
        const int r = tid >> 1;                 // 0..127
        const int c16 = (tid & 1) << 2;         // 0 or 4
#pragma unroll
        for (int p = 0; p < 4; p++) {
            const uint32_t col = (uint32_t)((c16 + p) * 16);
            const uint32_t sw = col ^ (uint32_t)((r & 7) << 4);
            CP16(smb + ASM_QH + r * 128 + sw, qgh + (size_t)r * DHEAD + (c16 + p) * 8);
            CP16(smb + ASM_QL + r * 128 + sw, qgl + (size_t)r * DHEAD + (c16 + p) * 8);
        }
        asm volatile("cp.async.commit_group;" ::: "memory");
        asm volatile("cp.async.wait_group 0;" ::: "memory");
    }
    __syncthreads();

    const int a_row = (lane & 7) + ((lane >> 3) & 1) * 8;
    const int a_colh = (lane >> 4) * 16;
    const int b_row = (lane & 7) + ((lane >> 4) & 1) * 8;
    const int b_colh = ((lane >> 3) & 1) * 16;
    const int t_krow = ((lane >> 3) & 1) * 8 + (lane & 7);
    const int t_ncol = ((lane >> 4) & 1) * 16;

    // Q hi fragments resident in registers
    uint32_t qa[4][4];
#pragma unroll
    for (int ks = 0; ks < 4; ks++) {
        const int r = w * 16 + a_row;
        const uint32_t col = (uint32_t)(ks * 32 + a_colh);
        LDSM4(qa[ks][0], qa[ks][1], qa[ks][2], qa[ks][3],
              smb + ASM_QH + r * 128 + (col ^ (uint32_t)((lane & 7) << 4)));
    }

    float o[8][4];
#pragma unroll
    for (int df = 0; df < 8; df++)
#pragma unroll
        for (int i = 0; i < 4; i++) o[df][i] = 0.f;
    float lsum0 = 0.f, lsum1 = 0.f;

    const int nkc = qt ? 4 : 2;
    const int wqg = qt * 128 + w * 16;
    const int r0 = wqg + (lane >> 2), r1 = r0 + 8;

    const __half* kgh = g_kh + hbase;
    const __half* vgh = g_vh + hbase;

#pragma unroll 1
    for (int kc = 0; kc < nkc; kc++) {
        __syncthreads();
        {
            const int r = tid >> 2;             // 0..63
            const int c16 = (tid & 3) << 1;     // 0,2,4,6
            const size_t src = (size_t)(kc * 64 + r) * DHEAD;
#pragma unroll
            for (int p = 0; p < 2; p++) {
                const uint32_t col = (uint32_t)((c16 + p) * 16);
                const uint32_t sw = (uint32_t)(r * 128) + (col ^ (uint32_t)((r & 7) << 4));
                CP16(smb + ASM_KH + sw, kgh + src + (c16 + p) * 8);
                CP16(smb + ASM_VH + sw, vgh + src + (c16 + p) * 8);
            }
            asm volatile("cp.async.commit_group;" ::: "memory");
            asm volatile("cp.async.wait_group 0;" ::: "memory");
        }
        __syncthreads();

        if (wqg + 15 < kc * 64) continue;

        // ---- S = (Qh + Ql).Kh^T, fp32 accum ----
        float S[8][4];
#pragma unroll
        for (int nf = 0; nf < 8; nf++)
#pragma unroll
            for (int i = 0; i < 4; i++) S[nf][i] = 0.f;

#pragma unroll
        for (int ks = 0; ks < 4; ks++) {
            uint32_t kb[8][2];
            const uint32_t colb = (uint32_t)(ks * 32 + b_colh);
#pragma unroll
            for (int g = 0; g < 4; g++) {
                const int r = g * 16 + b_row;
                LDSM4(kb[2 * g][0], kb[2 * g][1], kb[2 * g + 1][0], kb[2 * g + 1][1],
                      smb + ASM_KH + r * 128 + (colb ^ (uint32_t)((b_row & 7) << 4)));
            }
#pragma unroll
            for (int nf = 0; nf < 8; nf++)
                MMA16816(S[nf], qa[ks], kb[nf][0], kb[nf][1]);

            uint32_t ql4[4];
            {
                const int r = w * 16 + a_row;
                const uint32_t col = (uint32_t)(ks * 32 + a_colh);
                LDSM4(ql4[0], ql4[1], ql4[2], ql4[3],
                      smb + ASM_QL + r * 128 + (col ^ (uint32_t)((lane & 7) << 4)));
            }
#pragma unroll
            for (int nf = 0; nf < 8; nf++)
                MMA16816(S[nf], ql4, kb[nf][0], kb[nf][1]);
        }

        // ---- softmax (unnormalized, no max), causal mask ----
#pragma unroll
        for (int nf = 0; nf < 8; nf++) {
            const int c0 = kc * 64 + nf * 8 + (lane & 3) * 2;
            float p00 = (c0 <= r0)     ? __expf(S[nf][0] * 0.125f) : 0.f;
            float p01 = (c0 + 1 <= r0) ? __expf(S[nf][1] * 0.125f) : 0.f;
            float p10 = (c0 <= r1)     ? __expf(S[nf][2] * 0.125f) : 0.f;
            float p11 = (c0 + 1 <= r1) ? __expf(S[nf][3] * 0.125f) : 0.f;
            lsum0 += p00 + p01;
            lsum1 += p10 + p11;
            S[nf][0] = p00; S[nf][1] = p01; S[nf][2] = p10; S[nf][3] = p11;
        }

        // ---- O += (Ph + Pl).Vh ----
#pragma unroll
        for (int kj = 0; kj < 4; kj++) {
            uint32_t ph[4], pl[4];
            ph[0] = pk2f(S[2 * kj][0], S[2 * kj][1]);
            ph[1] = pk2f(S[2 * kj][2], S[2 * kj][3]);
            ph[2] = pk2f(S[2 * kj + 1][0], S[2 * kj + 1][1]);
            ph[3] = pk2f(S[2 * kj + 1][2], S[2 * kj + 1][3]);
            pl[0] = pk2lo(S[2 * kj][0], S[2 * kj][1]);
            pl[1] = pk2lo(S[2 * kj][2], S[2 * kj][3]);
            pl[2] = pk2lo(S[2 * kj + 1][0], S[2 * kj + 1][1]);
            pl[3] = pk2lo(S[2 * kj + 1][2], S[2 * kj + 1][3]);

            const int krow = kj * 16 + t_krow;
            uint32_t vb[8][2];
#pragma unroll
            for (int gd = 0; gd < 4; gd++) {
                const uint32_t col = (uint32_t)(gd * 32 + t_ncol);
                LDSM4T(vb[2 * gd][0], vb[2 * gd][1], vb[2 * gd + 1][0], vb[2 * gd + 1][1],
                       smb + ASM_VH + krow * 128 + (col ^ (uint32_t)((krow & 7) << 4)));
            }
#pragma unroll
            for (int df = 0; df < 8; df++)
                MMA16816(o[df], ph, vb[df][0], vb[df][1]);
#pragma unroll
            for (int df = 0; df < 8; df++)
                MMA16816(o[df], pl, vb[df][0], vb[df][1]);
        }
    }

    // ---- row-sum reduce over quad, normalize, split-write ----
    lsum0 += __shfl_xor_sync(0xffffffffu, lsum0, 1);
    lsum0 += __shfl_xor_sync(0xffffffffu, lsum0, 2);
    lsum1 += __shfl_xor_sync(0xffffffffu, lsum1, 1);
    lsum1 += __shfl_xor_sync(0xffffffffu, lsum1, 2);
    const float inv0 = 1.f / lsum0, inv1 = 1.f / lsum1;

    const int b = bh / NHEAD, h = bh - b * NHEAD;
    const size_t row0 = (size_t)(b * TT + r0) * CEMB + h * DHEAD;
    const size_t row1 = (size_t)(b * TT + r1) * CEMB + h * DHEAD;
#pragma unroll
    for (int df = 0; df < 8; df++) {
        const int d = df * 8 + (lane & 3) * 2;
        const float a0 = o[df][0] * inv0, a1 = o[df][1] * inv0;
        const float a2 = o[df][2] * inv1, a3 = o[df][3] * inv1;
        *(uint32_t*)&g_ahi[row0 + d] = pk2f(a0, a1);
        *(uint32_t*)&g_alo[row0 + d] = pk2lo(a0, a1);
        *(uint32_t*)&g_ahi[row1 + d] = pk2f(a2, a3);
        *(uint32_t*)&g_alo[row1 + d] = pk2lo(a2, a3);
    }
}

// ---------------------------------------------------------------------------
extern "C" void kernel_launch(void* const* d_in, const int* in_sizes, int n_in,
                              void* d_out, int out_size) {
    const float* x     = (const float*)d_in[0];
    const float* Wqkv  = (const float*)d_in[1];
    const float* Wproj = (const float*)d_in[2];
    const float* bproj = (const float*)d_in[3];
    float* out = (float*)d_out;

    cudaFuncSetAttribute(reinterpret_cast<const void*>(&gemm_mma<0>),
                         cudaFuncAttributeMaxDynamicSharedMemorySize, GSMEM_BYTES);
    cudaFuncSetAttribute(reinterpret_cast<const void*>(&gemm_mma<1>),
                         cudaFuncAttributeMaxDynamicSharedMemorySize, GSMEM_BYTES);
    cudaFuncSetAttribute(reinterpret_cast<const void*>(&attn_mma),
                         cudaFuncAttributeMaxDynamicSharedMemorySize, ASMEM_BYTES);

    conv_split<<<24576, 256>>>(x);
    conv_wT<3 * CEMB><<<3 * CEMB, CEMB>>>(Wqkv);
    conv_wT<CEMB><<<CEMB, CEMB>>>(Wproj);

    gemm_mma<0><<<dim3(9, 512), 256, GSMEM_BYTES>>>(nullptr, nullptr);
    attn_mma<<<dim3(2, 1536), 256, ASMEM_BYTES>>>();
    gemm_mma<1><<<dim3(3, 512), 256, GSMEM_BYTES>>>(bproj, out);
}

// round 16
// speedup vs baseline: 1.0835x; 1.0835x over previous
#include <cuda_runtime.h>
#include <cuda_fp16.h>
#include <cstdint>

#define NHEAD 6
#define DHEAD 64
#define CEMB  384
#define BB    256
#define TT    256
#define MROWS 65536

// ---------------- scratch (device globals: allocation-guard-safe) ----------
__device__ __align__(16) __half g_xhi[(size_t)MROWS * CEMB];    // x split
__device__ __align__(16) __half g_xlo[(size_t)MROWS * CEMB];
__device__ __align__(16) __half g_ahi[(size_t)MROWS * CEMB];    // attn out split
__device__ __align__(16) __half g_alo[(size_t)MROWS * CEMB];
__device__ __align__(16) __half g_wqh[(size_t)3 * CEMB * CEMB]; // Wqkv^T hi
__device__ __align__(16) __half g_wph[(size_t)CEMB * CEMB];     // Wproj^T hi
// q split, k/v hi only; layout [(b*NHEAD+h)*TT + t]*DHEAD + d
__device__ __align__(16) __half g_qh[(size_t)BB * NHEAD * TT * DHEAD];
__device__ __align__(16) __half g_ql[(size_t)BB * NHEAD * TT * DHEAD];
__device__ __align__(16) __half g_kh[(size_t)BB * NHEAD * TT * DHEAD];
__device__ __align__(16) __half g_vh[(size_t)BB * NHEAD * TT * DHEAD];

// ---------------- PTX helpers ----------------------------------------------
__device__ __forceinline__ uint32_t smem_u32(const void* p) {
    uint32_t a;
    asm("{ .reg .u64 t; cvta.to.shared.u64 t, %1; cvt.u32.u64 %0, t; }"
        : "=r"(a) : "l"(p));
    return a;
}

#define CP16(dst, src) \
    asm volatile("cp.async.cg.shared.global [%0], [%1], 16;" \
                 :: "r"(dst), "l"(src))

#define LDSM4(r0, r1, r2, r3, addr) \
    asm volatile("ldmatrix.sync.aligned.m8n8.x4.shared.b16 {%0,%1,%2,%3}, [%4];" \
                 : "=r"(r0), "=r"(r1), "=r"(r2), "=r"(r3) : "r"(addr))

#define LDSM4T(r0, r1, r2, r3, addr) \
    asm volatile("ldmatrix.sync.aligned.m8n8.x4.trans.shared.b16 {%0,%1,%2,%3}, [%4];" \
                 : "=r"(r0), "=r"(r1), "=r"(r2), "=r"(r3) : "r"(addr))

#define MMA16816(d, a, b0v, b1v) \
    asm volatile("mma.sync.aligned.m16n8k16.row.col.f32.f16.f16.f32 " \
                 "{%0,%1,%2,%3},{%4,%5,%6,%7},{%8,%9},{%0,%1,%2,%3};" \
                 : "+f"((d)[0]), "+f"((d)[1]), "+f"((d)[2]), "+f"((d)[3]) \
                 : "r"((a)[0]), "r"((a)[1]), "r"((a)[2]), "r"((a)[3]), \
                   "r"(b0v), "r"(b1v))

__device__ __forceinline__ uint32_t pk2f(float a, float b) {
    __half2 t = __floats2half2_rn(a, b);
    return *reinterpret_cast<uint32_t*>(&t);
}
__device__ __forceinline__ uint32_t pk2lo(float a, float b) {
    float ra = a - __half2float(__float2half_rn(a));
    float rb = b - __half2float(__float2half_rn(b));
    return pk2f(ra, rb);
}

// ---------------- conversion kernels ---------------------------------------
__global__ __launch_bounds__(256) void conv_split(const float* __restrict__ in) {
    const int i = blockIdx.x * 256 + threadIdx.x;
    float4 v = ((const float4*)in)[i];
    uint2 hp, lp;
    hp.x = pk2f(v.x, v.y); hp.y = pk2f(v.z, v.w);
    lp.x = pk2lo(v.x, v.y); lp.y = pk2lo(v.z, v.w);
    ((uint2*)g_xhi)[i] = hp;
    ((uint2*)g_xlo)[i] = lp;
}

template <int NN>
__global__ void conv_wT(const float* __restrict__ W) {
    const int n = blockIdx.x;
    const int k = threadIdx.x;
    float v = W[(size_t)k * NN + n];
    if (NN == 3 * CEMB) g_wqh[(size_t)n * CEMB + k] = __float2half_rn(v);
    else                g_wph[(size_t)n * CEMB + k] = __float2half_rn(v);
}

// ---------------- split-fp16 HMMA GEMM (2-term, 3-stage ring) ---------------
// MODE 0: scatter D into g_qh/g_ql/g_kh/g_vh.  MODE 1: D + bias -> out.
#define NCHUNK 12
#define STAGE_BYTES 32768
#define GSMEM_BYTES (3 * STAGE_BYTES + 1024)

template <int MODE>
__global__ __launch_bounds__(256) void gemm_mma(const float* __restrict__ bias,
                                                float* __restrict__ out) {
    extern __shared__ char dynraw[];
    char* sm = (char*)((((uintptr_t)dynraw) + 1023) & ~(uintptr_t)1023);
    const uint32_t smb = smem_u32(sm);

    const int tid = threadIdx.x;
    const int lane = tid & 31, wid = tid >> 5;
    const int wm = (wid & 3) * 32;
    const int wn = (wid >> 2) * 64;
    const int bn = blockIdx.x * 128, bm = blockIdx.y * 128;

    const __half* Ah = (MODE == 0) ? g_xhi : g_ahi;
    const __half* Al = (MODE == 0) ? g_xlo : g_alo;
    const __half* Bh = (MODE == 0) ? g_wqh : g_wph;

    const int a_row = (lane & 7) + ((lane >> 3) & 1) * 8;
    const int a_colh = (lane >> 4) * 16;
    const int b_row = (lane & 7) + ((lane >> 4) & 1) * 8;
    const int b_colh = ((lane >> 3) & 1) * 16;

    const int g_row0 = tid >> 3;
    const int g_c16 = tid & 7;
    const uint32_t g_dcol = (uint32_t)(g_c16 * 16);

    // stage chunk cn into ring slot cn%3 and commit as one group
    auto stage_chunk = [&](int cn) {
        const int blk = cn / 6, cb = cn - blk * 6;
        const __half* As = blk ? Al : Ah;
        const uint32_t sbase = smb + (uint32_t)((cn % 3) * STAGE_BYTES);
#pragma unroll
        for (int p = 0; p < 4; p++) {
            const int r = g_row0 + p * 32;
            const uint32_t d = sbase + r * 128 + (g_dcol ^ (uint32_t)((r & 7) << 4));
            CP16(d, As + (size_t)(bm + r) * CEMB + cb * 64 + g_c16 * 8);
            CP16(d + 16384, Bh + (size_t)(bn + r) * CEMB + cb * 64 + g_c16 * 8);
        }
        asm volatile("cp.async.commit_group;" ::: "memory");
    };

    float acc[2][8][4];
#pragma unroll
    for (int mf = 0; mf < 2; mf++)
#pragma unroll
        for (int nf = 0; nf < 8; nf++)
#pragma unroll
            for (int i = 0; i < 4; i++) acc[mf][nf][i] = 0.f;

    stage_chunk(0);
    stage_chunk(1);

#pragma unroll 1
    for (int c = 0; c < NCHUNK; c++) {
        if (c < NCHUNK - 1)
            asm volatile("cp.async.wait_group 1;" ::: "memory");
        else
            asm volatile("cp.async.wait_group 0;" ::: "memory");
        __syncthreads();   // the ONLY barrier per chunk

        const uint32_t abase = smb + (uint32_t)((c % 3) * STAGE_BYTES);
        const uint32_t bbase = abase + 16384;

#pragma unroll
        for (int ks = 0; ks < 4; ks++) {
            uint32_t af[2][4];
#pragma unroll
            for (int mf = 0; mf < 2; mf++) {
                const int r = wm + mf * 16 + a_row;
                const uint32_t col = (uint32_t)(ks * 32 + a_colh);
                const uint32_t ad = abase + r * 128 + (col ^ (uint32_t)((r & 7) << 4));
                LDSM4(af[mf][0], af[mf][1], af[mf][2], af[mf][3], ad);
            }
            uint32_t bf[8][2];
#pragma unroll
            for (int g = 0; g < 4; g++) {
                const int r = wn + g * 16 + b_row;
                const uint32_t col = (uint32_t)(ks * 32 + b_colh);
                const uint32_t bd = bbase + r * 128 + (col ^ (uint32_t)((r & 7) << 4));
                LDSM4(bf[2 * g][0], bf[2 * g][1], bf[2 * g + 1][0], bf[2 * g + 1][1], bd);
            }
#pragma unroll
            for (int mf = 0; mf < 2; mf++)
#pragma unroll
                for (int nf = 0; nf < 8; nf++)
                    MMA16816(acc[mf][nf], af[mf], bf[nf][0], bf[nf][1]);
        }

        if (c + 2 < NCHUNK) stage_chunk(c + 2);
    }

    if (MODE == 0) {
        const int sec = bn / CEMB;
        const int cc0 = bn - sec * CEMB;
        __half* dh = (sec == 0) ? g_qh : (sec == 1) ? g_kh : g_vh;
#pragma unroll
        for (int mf = 0; mf < 2; mf++) {
            const int m0 = bm + wm + mf * 16 + (lane >> 2);
#pragma unroll
            for (int nf = 0; nf < 8; nf++) {
                const int cc = cc0 + wn + nf * 8 + (lane & 3) * 2;
                const int h = cc >> 6, d = cc & 63;
#pragma unroll
                for (int hf = 0; hf < 2; hf++) {
                    const int m = m0 + hf * 8;
                    const int b = m >> 8, t = m & 255;
                    const float v0 = acc[mf][nf][hf * 2], v1 = acc[mf][nf][hf * 2 + 1];
                    const size_t idx = (((size_t)b * NHEAD + h) * TT + t) * DHEAD + d;
                    *(uint32_t*)&dh[idx] = pk2f(v0, v1);
                    if (sec == 0)
                        *(uint32_t*)&g_ql[idx] = pk2lo(v0, v1);
                }
            }
        }
    } else {
#pragma unroll
        for (int mf = 0; mf < 2; mf++) {
            const int m0 = bm + wm + mf * 16 + (lane >> 2);
#pragma unroll
            for (int nf = 0; nf < 8; nf++) {
                const int col = bn + wn + nf * 8 + (lane & 3) * 2;
                const float b0 = bias[col], b1 = bias[col + 1];
#pragma unroll
                for (int hf = 0; hf < 2; hf++) {
                    const int m = m0 + hf * 8;
                    float2 v = make_float2(acc[mf][nf][hf * 2] + b0,
                                           acc[mf][nf][hf * 2 + 1] + b1);
                    *(float2*)&out[(size_t)m * CEMB + col] = v;
                }
            }
        }
    }
}

// ---------------- split-fp16 mma flash attention -----------------------------
// grid (qtile=2, bh=1536), 8 warps; warp = 16 query rows x all keys.
// smem: QH 0, QL 16K (persistent); K/V double-buffered: buf s at 32K+s*16K
#define ASM_QH 0
#define ASM_QL 16384
#define ASM_KV(s) (32768 + (s) * 16384)   // KH at +0 (8K), VH at +8192
#define ASMEM_BYTES 65536

__global__ __launch_bounds__(256) void attn_mma() {
    extern __shared__ __align__(16) char asm_raw[];
    const uint32_t smb = smem_u32(asm_raw);

    const int tid = threadIdx.x;
    const int lane = tid & 31, w = tid >> 5;
    const int qt = blockIdx.x;          // 0..1
    const int bh = blockIdx.y;          // 0..1535

    const size_t hbase = (size_t)bh * TT * DHEAD;
    const __half* qgh = g_qh + hbase + (size_t)qt * 128 * DHEAD;
    const __half* qgl = g_ql + hbase + (size_t)qt * 128 * DHEAD;
    const __half* kgh = g_kh + hbase;
    const __half* vgh = g_vh + hbase;

    const int nkc = qt ? 4 : 2;

    // stage K/V chunk kc into buffer kc&1 and commit
    auto stage_kv = [&](int kc) {
        const int r = tid >> 2;             // 0..63
        const int c16 = (tid & 3) << 1;     // 0,2,4,6
        const size_t src = (size_t)(kc * 64 + r) * DHEAD;
        const uint32_t kvb = smb + (uint32_t)ASM_KV(kc & 1);
#pragma unroll
        for (int p = 0; p < 2; p++) {
            const uint32_t col = (uint32_t)((c16 + p) * 16);
            const uint32_t sw = (uint32_t)(r * 128) + (col ^ (uint32_t)((r & 7) << 4));
            CP16(kvb + sw, kgh + src + (c16 + p) * 8);
            CP16(kvb + 8192 + sw, vgh + src + (c16 + p) * 8);
        }
        asm volatile("cp.async.commit_group;" ::: "memory");
    };

    // stage Q (hi+lo), then K/V chunk 0; wait for both
    {
        const int r = tid >> 1;                 // 0..127
        const int c16 = (tid & 1) << 2;         // 0 or 4
#pragma unroll
        for (int p = 0; p < 4; p++) {
            const uint32_t col = (uint32_t)((c16 + p) * 16);
            const uint32_t sw = col ^ (uint32_t)((r & 7) << 4);
            CP16(smb + ASM_QH + r * 128 + sw, qgh + (size_t)r * DHEAD + (c16 + p) * 8);
            CP16(smb + ASM_QL + r * 128 + sw, qgl + (size_t)r * DHEAD + (c16 + p) * 8);
        }
        asm volatile("cp.async.commit_group;" ::: "memory");
    }
    stage_kv(0);
    asm volatile("cp.async.wait_group 0;" ::: "memory");
    __syncthreads();

    const int a_row = (lane & 7) + ((lane >> 3) & 1) * 8;
    const int a_colh = (lane >> 4) * 16;
    const int b_row = (lane & 7) + ((lane >> 4) & 1) * 8;
    const int b_colh = ((lane >> 3) & 1) * 16;
    const int t_krow = ((lane >> 3) & 1) * 8 + (lane & 7);
    const int t_ncol = ((lane >> 4) & 1) * 16;

    // Q hi fragments resident in registers
    uint32_t qa[4][4];
#pragma unroll
    for (int ks = 0; ks < 4; ks++) {
        const int r = w * 16 + a_row;
        const uint32_t col = (uint32_t)(ks * 32 + a_colh);
        LDSM4(qa[ks][0], qa[ks][1], qa[ks][2], qa[ks][3],
              smb + ASM_QH + r * 128 + (col ^ (uint32_t)((lane & 7) << 4)));
    }

    float o[8][4];
#pragma unroll
    for (int df = 0; df < 8; df++)
#pragma unroll
        for (int i = 0; i < 4; i++) o[df][i] = 0.f;
    float lsum0 = 0.f, lsum1 = 0.f;

    const int wqg = qt * 128 + w * 16;
    const int r0 = wqg + (lane >> 2), r1 = r0 + 8;

#pragma unroll 1
    for (int kc = 0; kc < nkc; kc++) {
        // prefetch next chunk into the other buffer (ordered vs its last
        // readers by the trailing __syncthreads of iteration kc-1)
        if (kc + 1 < nkc) {
            stage_kv(kc + 1);
            asm volatile("cp.async.wait_group 1;" ::: "memory");
        } else {
            asm volatile("cp.async.wait_group 0;" ::: "memory");
        }
        __syncthreads();

        if (wqg + 15 >= kc * 64) {          // warp not fully masked
            const uint32_t kbb = smb + (uint32_t)ASM_KV(kc & 1);
            const uint32_t vbb = kbb + 8192;

            // ---- S = (Qh + Ql).Kh^T, fp32 accum ----
            float S[8][4];
#pragma unroll
            for (int nf = 0; nf < 8; nf++)
#pragma unroll
                for (int i = 0; i < 4; i++) S[nf][i] = 0.f;

#pragma unroll
            for (int ks = 0; ks < 4; ks++) {
                uint32_t kb[8][2];
                const uint32_t colb = (uint32_t)(ks * 32 + b_colh);
#pragma unroll
                for (int g = 0; g < 4; g++) {
                    const int r = g * 16 + b_row;
                    LDSM4(kb[2 * g][0], kb[2 * g][1], kb[2 * g + 1][0], kb[2 * g + 1][1],
                          kbb + r * 128 + (colb ^ (uint32_t)((b_row & 7) << 4)));
                }
#pragma unroll
                for (int nf = 0; nf < 8; nf++)
                    MMA16816(S[nf], qa[ks], kb[nf][0], kb[nf][1]);

                uint32_t ql4[4];
                {
                    const int r = w * 16 + a_row;
                    const uint32_t col = (uint32_t)(ks * 32 + a_colh);
                    LDSM4(ql4[0], ql4[1], ql4[2], ql4[3],
                          smb + ASM_QL + r * 128 + (col ^ (uint32_t)((lane & 7) << 4)));
                }
#pragma unroll
                for (int nf = 0; nf < 8; nf++)
                    MMA16816(S[nf], ql4, kb[nf][0], kb[nf][1]);
            }

            // ---- softmax (unnormalized, no max), causal mask ----
#pragma unroll
            for (int nf = 0; nf < 8; nf++) {
                const int c0 = kc * 64 + nf * 8 + (lane & 3) * 2;
                float p00 = (c0 <= r0)     ? __expf(S[nf][0] * 0.125f) : 0.f;
                float p01 = (c0 + 1 <= r0) ? __expf(S[nf][1] * 0.125f) : 0.f;
                float p10 = (c0 <= r1)     ? __expf(S[nf][2] * 0.125f) : 0.f;
                float p11 = (c0 + 1 <= r1) ? __expf(S[nf][3] * 0.125f) : 0.f;
                lsum0 += p00 + p01;
                lsum1 += p10 + p11;
                S[nf][0] = p00; S[nf][1] = p01; S[nf][2] = p10; S[nf][3] = p11;
            }

            // ---- O += (Ph + Pl).Vh ----
#pragma unroll
            for (int kj = 0; kj < 4; kj++) {
                uint32_t ph[4], pl[4];
                ph[0] = pk2f(S[2 * kj][0], S[2 * kj][1]);
                ph[1] = pk2f(S[2 * kj][2], S[2 * kj][3]);
                ph[2] = pk2f(S[2 * kj + 1][0], S[2 * kj + 1][1]);
                ph[3] = pk2f(S[2 * kj + 1][2], S[2 * kj + 1][3]);
                pl[0] = pk2lo(S[2 * kj][0], S[2 * kj][1]);
                pl[1] = pk2lo(S[2 * kj][2], S[2 * kj][3]);
                pl[2] = pk2lo(S[2 * kj + 1][0], S[2 * kj + 1][1]);
                pl[3] = pk2lo(S[2 * kj + 1][2], S[2 * kj + 1][3]);

                const int krow = kj * 16 + t_krow;
                uint32_t vb[8][2];
#pragma unroll
                for (int gd = 0; gd < 4; gd++) {
                    const uint32_t col = (uint32_t)(gd * 32 + t_ncol);
                    LDSM4T(vb[2 * gd][0], vb[2 * gd][1], vb[2 * gd + 1][0], vb[2 * gd + 1][1],
                           vbb + krow * 128 + (col ^ (uint32_t)((krow & 7) << 4)));
                }
#pragma unroll
                for (int df = 0; df < 8; df++)
                    MMA16816(o[df], ph, vb[df][0], vb[df][1]);
#pragma unroll
                for (int df = 0; df < 8; df++)
                    MMA16816(o[df], pl, vb[df][0], vb[df][1]);
            }
        }
        __syncthreads();   // buffer kc&1 free for re-staging at iter kc+1
    }

    // ---- row-sum reduce over quad, normalize, split-write ----
    lsum0 += __shfl_xor_sync(0xffffffffu, lsum0, 1);
    lsum0 += __shfl_xor_sync(0xffffffffu, lsum0, 2);
    lsum1 += __shfl_xor_sync(0xffffffffu, lsum1, 1);
    lsum1 += __shfl_xor_sync(0xffffffffu, lsum1, 2);
    const float inv0 = 1.f / lsum0, inv1 = 1.f / lsum1;

    const int b = bh / NHEAD, h = bh - b * NHEAD;
    const size_t row0 = (size_t)(b * TT + r0) * CEMB + h * DHEAD;
    const size_t row1 = (size_t)(b * TT + r1) * CEMB + h * DHEAD;
#pragma unroll
    for (int df = 0; df < 8; df++) {
        const int d = df * 8 + (lane & 3) * 2;
        const float a0 = o[df][0] * inv0, a1 = o[df][1] * inv0;
        const float a2 = o[df][2] * inv1, a3 = o[df][3] * inv1;
        *(uint32_t*)&g_ahi[row0 + d] = pk2f(a0, a1);
        *(uint32_t*)&g_alo[row0 + d] = pk2lo(a0, a1);
        *(uint32_t*)&g_ahi[row1 + d] = pk2f(a2, a3);
        *(uint32_t*)&g_alo[row1 + d] = pk2lo(a2, a3);
    }
}

// ---------------------------------------------------------------------------
extern "C" void kernel_launch(void* const* d_in, const int* in_sizes, int n_in,
                              void* d_out, int out_size) {
    const float* x     = (const float*)d_in[0];
    const float* Wqkv  = (const float*)d_in[1];
    const float* Wproj = (const float*)d_in[2];
    const float* bproj = (const float*)d_in[3];
    float* out = (float*)d_out;

    cudaFuncSetAttribute(reinterpret_cast<const void*>(&gemm_mma<0>),
                         cudaFuncAttributeMaxDynamicSharedMemorySize, GSMEM_BYTES);
    cudaFuncSetAttribute(reinterpret_cast<const void*>(&gemm_mma<1>),
                         cudaFuncAttributeMaxDynamicSharedMemorySize, GSMEM_BYTES);
    cudaFuncSetAttribute(reinterpret_cast<const void*>(&attn_mma),
                         cudaFuncAttributeMaxDynamicSharedMemorySize, ASMEM_BYTES);

    conv_split<<<24576, 256>>>(x);
    conv_wT<3 * CEMB><<<3 * CEMB, CEMB>>>(Wqkv);
    conv_wT<CEMB><<<CEMB, CEMB>>>(Wproj);

    gemm_mma<0><<<dim3(9, 512), 256, GSMEM_BYTES>>>(nullptr, nullptr);
    attn_mma<<<dim3(2, 1536), 256, ASMEM_BYTES>>>();
    gemm_mma<1><<<dim3(3, 512), 256, GSMEM_BYTES>>>(bproj, out);
}

// round 17
// speedup vs baseline: 1.7091x; 1.5774x over previous
#include <cuda_runtime.h>
#include <cuda_fp16.h>
#include <cstdint>

#define NHEAD 6
#define DHEAD 64
#define CEMB  384
#define BB    256
#define TT    256
#define MROWS 65536

// ---------------- scratch (device globals: allocation-guard-safe) ----------
__device__ __align__(16) __half g_xh[(size_t)MROWS * CEMB];     // x fp16
__device__ __align__(16) __half g_ah[(size_t)MROWS * CEMB];     // attn out fp16
__device__ __align__(16) __half g_wqh[(size_t)3 * CEMB * CEMB]; // Wqkv^T fp16
__device__ __align__(16) __half g_wph[(size_t)CEMB * CEMB];     // Wproj^T fp16
// layout [(b*NHEAD+h)*TT + t]*DHEAD + d
__device__ __align__(16) __half g_qh[(size_t)BB * NHEAD * TT * DHEAD];
__device__ __align__(16) __half g_kh[(size_t)BB * NHEAD * TT * DHEAD];
__device__ __align__(16) __half g_vh[(size_t)BB * NHEAD * TT * DHEAD];

// ---------------- PTX helpers ----------------------------------------------
__device__ __forceinline__ uint32_t smem_u32(const void* p) {
    uint32_t a;
    asm("{ .reg .u64 t; cvta.to.shared.u64 t, %1; cvt.u32.u64 %0, t; }"
        : "=r"(a) : "l"(p));
    return a;
}

#define CP16(dst, src) \
    asm volatile("cp.async.cg.shared.global [%0], [%1], 16;" \
                 :: "r"(dst), "l"(src))

#define LDSM4(r0, r1, r2, r3, addr) \
    asm volatile("ldmatrix.sync.aligned.m8n8.x4.shared.b16 {%0,%1,%2,%3}, [%4];" \
                 : "=r"(r0), "=r"(r1), "=r"(r2), "=r"(r3) : "r"(addr))

#define LDSM4T(r0, r1, r2, r3, addr) \
    asm volatile("ldmatrix.sync.aligned.m8n8.x4.trans.shared.b16 {%0,%1,%2,%3}, [%4];" \
                 : "=r"(r0), "=r"(r1), "=r"(r2), "=r"(r3) : "r"(addr))

#define MMA16816(d, a, b0v, b1v) \
    asm volatile("mma.sync.aligned.m16n8k16.row.col.f32.f16.f16.f32 " \
                 "{%0,%1,%2,%3},{%4,%5,%6,%7},{%8,%9},{%0,%1,%2,%3};" \
                 : "+f"((d)[0]), "+f"((d)[1]), "+f"((d)[2]), "+f"((d)[3]) \
                 : "r"((a)[0]), "r"((a)[1]), "r"((a)[2]), "r"((a)[3]), \
                   "r"(b0v), "r"(b1v))

__device__ __forceinline__ uint32_t pk2f(float a, float b) {
    __half2 t = __floats2half2_rn(a, b);
    return *reinterpret_cast<uint32_t*>(&t);
}

// ---------------- conversion kernels ---------------------------------------
__global__ __launch_bounds__(256) void conv_half(const float* __restrict__ in) {
    const int i = blockIdx.x * 256 + threadIdx.x;
    float4 v = ((const float4*)in)[i];
    uint2 hp;
    hp.x = pk2f(v.x, v.y); hp.y = pk2f(v.z, v.w);
    ((uint2*)g_xh)[i] = hp;
}

template <int NN>
__global__ void conv_wT(const float* __restrict__ W) {
    const int n = blockIdx.x;
    const int k = threadIdx.x;
    float v = W[(size_t)k * NN + n];
    if (NN == 3 * CEMB) g_wqh[(size_t)n * CEMB + k] = __float2half_rn(v);
    else                g_wph[(size_t)n * CEMB + k] = __float2half_rn(v);
}

// ---------------- fp16 HMMA GEMM (K=384, 3-stage ring) ----------------------
// MODE 0: scatter D into g_qh/g_kh/g_vh.  MODE 1: D + bias -> out.
#define NCHUNK 6
#define STAGE_BYTES 32768
#define GSMEM_BYTES (3 * STAGE_BYTES + 1024)

template <int MODE>
__global__ __launch_bounds__(256) void gemm_mma(const float* __restrict__ bias,
                                                float* __restrict__ out) {
    extern __shared__ char dynraw[];
    char* sm = (char*)((((uintptr_t)dynraw) + 1023) & ~(uintptr_t)1023);
    const uint32_t smb = smem_u32(sm);

    const int tid = threadIdx.x;
    const int lane = tid & 31, wid = tid >> 5;
    const int wm = (wid & 3) * 32;
    const int wn = (wid >> 2) * 64;
    const int bn = blockIdx.x * 128, bm = blockIdx.y * 128;

    const __half* Ah = (MODE == 0) ? g_xh : g_ah;
    const __half* Bh = (MODE == 0) ? g_wqh : g_wph;

    const int a_row = (lane & 7) + ((lane >> 3) & 1) * 8;
    const int a_colh = (lane >> 4) * 16;
    const int b_row = (lane & 7) + ((lane >> 4) & 1) * 8;
    const int b_colh = ((lane >> 3) & 1) * 16;

    const int g_row0 = tid >> 3;
    const int g_c16 = tid & 7;
    const uint32_t g_dcol = (uint32_t)(g_c16 * 16);

    // stage chunk cn (64 K-cols) into ring slot cn%3, one commit group
    auto stage_chunk = [&](int cn) {
        const uint32_t sbase = smb + (uint32_t)((cn % 3) * STAGE_BYTES);
#pragma unroll
        for (int p = 0; p < 4; p++) {
            const int r = g_row0 + p * 32;
            const uint32_t d = sbase + r * 128 + (g_dcol ^ (uint32_t)((r & 7) << 4));
            CP16(d, Ah + (size_t)(bm + r) * CEMB + cn * 64 + g_c16 * 8);
            CP16(d + 16384, Bh + (size_t)(bn + r) * CEMB + cn * 64 + g_c16 * 8);
        }
        asm volatile("cp.async.commit_group;" ::: "memory");
    };

    float acc[2][8][4];
#pragma unroll
    for (int mf = 0; mf < 2; mf++)
#pragma unroll
        for (int nf = 0; nf < 8; nf++)
#pragma unroll
            for (int i = 0; i < 4; i++) acc[mf][nf][i] = 0.f;

    stage_chunk(0);
    stage_chunk(1);

#pragma unroll 1
    for (int c = 0; c < NCHUNK; c++) {
        if (c < NCHUNK - 1)
            asm volatile("cp.async.wait_group 1;" ::: "memory");
        else
            asm volatile("cp.async.wait_group 0;" ::: "memory");
        __syncthreads();   // the ONLY barrier per chunk

        const uint32_t abase = smb + (uint32_t)((c % 3) * STAGE_BYTES);
        const uint32_t bbase = abase + 16384;

#pragma unroll
        for (int ks = 0; ks < 4; ks++) {
            uint32_t af[2][4];
#pragma unroll
            for (int mf = 0; mf < 2; mf++) {
                const int r = wm + mf * 16 + a_row;
                const uint32_t col = (uint32_t)(ks * 32 + a_colh);
                const uint32_t ad = abase + r * 128 + (col ^ (uint32_t)((r & 7) << 4));
                LDSM4(af[mf][0], af[mf][1], af[mf][2], af[mf][3], ad);
            }
            uint32_t bf[8][2];
#pragma unroll
            for (int g = 0; g < 4; g++) {
                const int r = wn + g * 16 + b_row;
                const uint32_t col = (uint32_t)(ks * 32 + b_colh);
                const uint32_t bd = bbase + r * 128 + (col ^ (uint32_t)((r & 7) << 4));
                LDSM4(bf[2 * g][0], bf[2 * g][1], bf[2 * g + 1][0], bf[2 * g + 1][1], bd);
            }
#pragma unroll
            for (int mf = 0; mf < 2; mf++)
#pragma unroll
                for (int nf = 0; nf < 8; nf++)
                    MMA16816(acc[mf][nf], af[mf], bf[nf][0], bf[nf][1]);
        }

        if (c + 2 < NCHUNK) stage_chunk(c + 2);
    }

    if (MODE == 0) {
        const int sec = bn / CEMB;
        const int cc0 = bn - sec * CEMB;
        __half* dh = (sec == 0) ? g_qh : (sec == 1) ? g_kh : g_vh;
#pragma unroll
        for (int mf = 0; mf < 2; mf++) {
            const int m0 = bm + wm + mf * 16 + (lane >> 2);
#pragma unroll
            for (int nf = 0; nf < 8; nf++) {
                const int cc = cc0 + wn + nf * 8 + (lane & 3) * 2;
                const int h = cc >> 6, d = cc & 63;
#pragma unroll
                for (int hf = 0; hf < 2; hf++) {
                    const int m = m0 + hf * 8;
                    const int b = m >> 8, t = m & 255;
                    const size_t idx = (((size_t)b * NHEAD + h) * TT + t) * DHEAD + d;
                    *(uint32_t*)&dh[idx] = pk2f(acc[mf][nf][hf * 2], acc[mf][nf][hf * 2 + 1]);
                }
            }
        }
    } else {
#pragma unroll
        for (int mf = 0; mf < 2; mf++) {
            const int m0 = bm + wm + mf * 16 + (lane >> 2);
#pragma unroll
            for (int nf = 0; nf < 8; nf++) {
                const int col = bn + wn + nf * 8 + (lane & 3) * 2;
                const float b0 = bias[col], b1 = bias[col + 1];
#pragma unroll
                for (int hf = 0; hf < 2; hf++) {
                    const int m = m0 + hf * 8;
                    float2 v = make_float2(acc[mf][nf][hf * 2] + b0,
                                           acc[mf][nf][hf * 2 + 1] + b1);
                    *(float2*)&out[(size_t)m * CEMB + col] = v;
                }
            }
        }
    }
}

// ---------------- fp16 mma flash attention ----------------------------------
// grid (qtile=2, bh=1536), 8 warps; warp = 16 query rows x all keys.
// smem: QH 0..16K (persistent); K/V double-buffered at 16K + s*16K
#define ASM_QH 0
#define ASM_KV(s) (16384 + (s) * 16384)   // KH at +0 (8K), VH at +8192
#define ASMEM_BYTES 49152

__global__ __launch_bounds__(256) void attn_mma() {
    extern __shared__ __align__(16) char asm_raw[];
    const uint32_t smb = smem_u32(asm_raw);

    const int tid = threadIdx.x;
    const int lane = tid & 31, w = tid >> 5;
    const int qt = blockIdx.x;          // 0..1
    const int bh = blockIdx.y;          // 0..1535

    const size_t hbase = (size_t)bh * TT * DHEAD;
    const __half* qgh = g_qh + hbase + (size_t)qt * 128 * DHEAD;
    const __half* kgh = g_kh + hbase;
    const __half* vgh = g_vh + hbase;

    const int nkc = qt ? 4 : 2;

    // stage K/V chunk kc into buffer kc&1 and commit
    auto stage_kv = [&](int kc) {
        const int r = tid >> 2;             // 0..63
        const int c16 = (tid & 3) << 1;     // 0,2,4,6
        const size_t src = (size_t)(kc * 64 + r) * DHEAD;
        const uint32_t kvb = smb + (uint32_t)ASM_KV(kc & 1);
#pragma unroll
        for (int p = 0; p < 2; p++) {
            const uint32_t col = (uint32_t)((c16 + p) * 16);
            const uint32_t sw = (uint32_t)(r * 128) + (col ^ (uint32_t)((r & 7) << 4));
            CP16(kvb + sw, kgh + src + (c16 + p) * 8);
            CP16(kvb + 8192 + sw, vgh + src + (c16 + p) * 8);
        }
        asm volatile("cp.async.commit_group;" ::: "memory");
    };

    // stage Q, then K/V chunk 0; wait for both
    {
        const int r = tid >> 1;                 // 0..127
        const int c16 = (tid & 1) << 2;         // 0 or 4
#pragma unroll
        for (int p = 0; p < 4; p++) {
            const uint32_t col = (uint32_t)((c16 + p) * 16);
            const uint32_t sw = col ^ (uint32_t)((r & 7) << 4);
            CP16(smb + ASM_QH + r * 128 + sw, qgh + (size_t)r * DHEAD + (c16 + p) * 8);
        }
        asm volatile("cp.async.commit_group;" ::: "memory");
    }
    stage_kv(0);
    asm volatile("cp.async.wait_group 0;" ::: "memory");
    __syncthreads();

    const int a_row = (lane & 7) + ((lane >> 3) & 1) * 8;
    const int a_colh = (lane >> 4) * 16;
    const int b_row = (lane & 7) + ((lane >> 4) & 1) * 8;
    const int b_colh = ((lane >> 3) & 1) * 16;
    const int t_krow = ((lane >> 3) & 1) * 8 + (lane & 7);
    const int t_ncol = ((lane >> 4) & 1) * 16;

    // Q fragments resident in registers
    uint32_t qa[4][4];
#pragma unroll
    for (int ks = 0; ks < 4; ks++) {
        const int r = w * 16 + a_row;
        const uint32_t col = (uint32_t)(ks * 32 + a_colh);
        LDSM4(qa[ks][0], qa[ks][1], qa[ks][2], qa[ks][3],
              smb + ASM_QH + r * 128 + (col ^ (uint32_t)((lane & 7) << 4)));
    }

    float o[8][4];
#pragma unroll
    for (int df = 0; df < 8; df++)
#pragma unroll
        for (int i = 0; i < 4; i++) o[df][i] = 0.f;
    float lsum0 = 0.f, lsum1 = 0.f;

    const int wqg = qt * 128 + w * 16;
    const int r0 = wqg + (lane >> 2), r1 = r0 + 8;

#pragma unroll 1
    for (int kc = 0; kc < nkc; kc++) {
        if (kc + 1 < nkc) {
            stage_kv(kc + 1);
            asm volatile("cp.async.wait_group 1;" ::: "memory");
        } else {
            asm volatile("cp.async.wait_group 0;" ::: "memory");
        }
        __syncthreads();

        if (wqg + 15 >= kc * 64) {          // warp not fully masked
            const uint32_t kbb = smb + (uint32_t)ASM_KV(kc & 1);
            const uint32_t vbb = kbb + 8192;

            // ---- S = Q.K^T, fp32 accum ----
            float S[8][4];
#pragma unroll
            for (int nf = 0; nf < 8; nf++)
#pragma unroll
                for (int i = 0; i < 4; i++) S[nf][i] = 0.f;

#pragma unroll
            for (int ks = 0; ks < 4; ks++) {
                uint32_t kb[8][2];
                const uint32_t colb = (uint32_t)(ks * 32 + b_colh);
#pragma unroll
                for (int g = 0; g < 4; g++) {
                    const int r = g * 16 + b_row;
                    LDSM4(kb[2 * g][0], kb[2 * g][1], kb[2 * g + 1][0], kb[2 * g + 1][1],
                          kbb + r * 128 + (colb ^ (uint32_t)((b_row & 7) << 4)));
                }
#pragma unroll
                for (int nf = 0; nf < 8; nf++)
                    MMA16816(S[nf], qa[ks], kb[nf][0], kb[nf][1]);
            }

            // ---- softmax (unnormalized, no max), causal mask ----
#pragma unroll
            for (int nf = 0; nf < 8; nf++) {
                const int c0 = kc * 64 + nf * 8 + (lane & 3) * 2;
                float p00 = (c0 <= r0)     ? __expf(S[nf][0] * 0.125f) : 0.f;
                float p01 = (c0 + 1 <= r0) ? __expf(S[nf][1] * 0.125f) : 0.f;
                float p10 = (c0 <= r1)     ? __expf(S[nf][2] * 0.125f) : 0.f;
                float p11 = (c0 + 1 <= r1) ? __expf(S[nf][3] * 0.125f) : 0.f;
                lsum0 += p00 + p01;
                lsum1 += p10 + p11;
                S[nf][0] = p00; S[nf][1] = p01; S[nf][2] = p10; S[nf][3] = p11;
            }

            // ---- O += P.V ----
#pragma unroll
            for (int kj = 0; kj < 4; kj++) {
                uint32_t ph[4];
                ph[0] = pk2f(S[2 * kj][0], S[2 * kj][1]);
                ph[1] = pk2f(S[2 * kj][2], S[2 * kj][3]);
                ph[2] = pk2f(S[2 * kj + 1][0], S[2 * kj + 1][1]);
                ph[3] = pk2f(S[2 * kj + 1][2], S[2 * kj + 1][3]);

                const int krow = kj * 16 + t_krow;
                uint32_t vb[8][2];
#pragma unroll
                for (int gd = 0; gd < 4; gd++) {
                    const uint32_t col = (uint32_t)(gd * 32 + t_ncol);
                    LDSM4T(vb[2 * gd][0], vb[2 * gd][1], vb[2 * gd + 1][0], vb[2 * gd + 1][1],
                           vbb + krow * 128 + (col ^ (uint32_t)((krow & 7) << 4)));
                }
#pragma unroll
                for (int df = 0; df < 8; df++)
                    MMA16816(o[df], ph, vb[df][0], vb[df][1]);
            }
        }
        __syncthreads();   // buffer kc&1 free for re-staging at iter kc+1
    }

    // ---- row-sum reduce over quad, normalize, write fp16 ----
    lsum0 += __shfl_xor_sync(0xffffffffu, lsum0, 1);
    lsum0 += __shfl_xor_sync(0xffffffffu, lsum0, 2);
    lsum1 += __shfl_xor_sync(0xffffffffu, lsum1, 1);
    lsum1 += __shfl_xor_sync(0xffffffffu, lsum1, 2);
    const float inv0 = 1.f / lsum0, inv1 = 1.f / lsum1;

    const int b = bh / NHEAD, h = bh - b * NHEAD;
    const size_t row0 = (size_t)(b * TT + r0) * CEMB + h * DHEAD;
    const size_t row1 = (size_t)(b * TT + r1) * CEMB + h * DHEAD;
#pragma unroll
    for (int df = 0; df < 8; df++) {
        const int d = df * 8 + (lane & 3) * 2;
        *(uint32_t*)&g_ah[row0 + d] = pk2f(o[df][0] * inv0, o[df][1] * inv0);
        *(uint32_t*)&g_ah[row1 + d] = pk2f(o[df][2] * inv1, o[df][3] * inv1);
    }
}

// ---------------------------------------------------------------------------
extern "C" void kernel_launch(void* const* d_in, const int* in_sizes, int n_in,
                              void* d_out, int out_size) {
    const float* x     = (const float*)d_in[0];
    const float* Wqkv  = (const float*)d_in[1];
    const float* Wproj = (const float*)d_in[2];
    const float* bproj = (const float*)d_in[3];
    float* out = (float*)d_out;

    cudaFuncSetAttribute(reinterpret_cast<const void*>(&gemm_mma<0>),
                         cudaFuncAttributeMaxDynamicSharedMemorySize, GSMEM_BYTES);
    cudaFuncSetAttribute(reinterpret_cast<const void*>(&gemm_mma<1>),
                         cudaFuncAttributeMaxDynamicSharedMemorySize, GSMEM_BYTES);
    cudaFuncSetAttribute(reinterpret_cast<const void*>(&attn_mma),
                         cudaFuncAttributeMaxDynamicSharedMemorySize, ASMEM_BYTES);

    conv_half<<<24576, 256>>>(x);
    conv_wT<3 * CEMB><<<3 * CEMB, CEMB>>>(Wqkv);
    conv_wT<CEMB><<<CEMB, CEMB>>>(Wproj);

    gemm_mma<0><<<dim3(9, 512), 256, GSMEM_BYTES>>>(nullptr, nullptr);
    attn_mma<<<dim3(2, 1536), 256, ASMEM_BYTES>>>();
    gemm_mma<1><<<dim3(3, 512), 256, GSMEM_BYTES>>>(bproj, out);
}